// round 5
// baseline (speedup 1.0000x reference)
#include <cuda_runtime.h>
#include <cuda_fp16.h>
#include <cstdint>
#include <cstddef>

#define D 128
#define MAXN 50000
#define MAXE 800000
#define TILE_N 64
#define TTHREADS 512
#define BN_EPS 1e-5f
#define SCAN_B 1024
#define NBLK ((MAXN + SCAN_B - 1) / SCAN_B)   // 49

// ---------------- device scratch ----------------
__device__ float  g_agg[(size_t)MAXN * D];   // mean of neighbor features (fp32)
__device__ float  g_h[(size_t)MAXN * D];     // layer-1 pre-BN output (fp32, exact)
__device__ __half g_xh[(size_t)MAXN * D];    // fp16 shadow of x (gather input, layer 1)
__device__ __half g_hh[(size_t)MAXN * D];    // fp16 shadow of h (gather input, layer 2)
__device__ int    g_cnt[MAXN];
__device__ int    g_offs[MAXN + 1];
__device__ int    g_cur[MAXN];
__device__ int    g_bsum[NBLK];
__device__ int    g_esrc[MAXE];
__device__ float  g_wt1[2 * D * D];          // [k][j] transposed [w1_l; w1_r]
__device__ float  g_wt2[2 * D * D];
__device__ float  g_colsum[D], g_colsumsq[D], g_scale[D], g_shift[D];

// ---------------- helpers ----------------
__device__ __forceinline__ void red_add1(float* p, float v) {
    asm volatile("red.global.add.f32 [%0], %1;" :: "l"(p), "f"(v) : "memory");
}
__device__ __forceinline__ unsigned long long fma2(unsigned long long a,
                                                   unsigned long long b,
                                                   unsigned long long c) {
    unsigned long long d;
    asm("fma.rn.f32x2 %0, %1, %2, %3;" : "=l"(d) : "l"(a), "l"(b), "l"(c));
    return d;
}
__device__ __forceinline__ unsigned long long splat2(float x) {
    unsigned long long d;
    asm("mov.b64 %0, {%1, %1};" : "=l"(d) : "f"(x));
    return d;
}
__device__ __forceinline__ void lds_v2b64(unsigned long long& a, unsigned long long& b,
                                          unsigned int addr) {
    asm("ld.shared.v2.b64 {%0, %1}, [%2];" : "=l"(a), "=l"(b) : "r"(addr));
}
__device__ __forceinline__ void lds_v4f(float& a, float& b, float& c, float& d,
                                        unsigned int addr) {
    asm("ld.shared.v4.b32 {%0, %1, %2, %3}, [%4];"
        : "=f"(a), "=f"(b), "=f"(c), "=f"(d) : "r"(addr));
}
__device__ __forceinline__ void unpack2(unsigned long long v, float& lo, float& hi) {
    asm("mov.b64 {%0, %1}, %2;" : "=f"(lo), "=f"(hi) : "l"(v));
}

// ---------------- fp32 -> fp16 shadow of x ----------------
__global__ void conv_half_k(const float* __restrict__ x, int n4) {
    int i = blockIdx.x * blockDim.x + threadIdx.x;
    if (i >= n4) return;
    float4 v = __ldg((const float4*)x + i);
    __half2* o = (__half2*)g_xh + (size_t)i * 2;
    o[0] = __floats2half2_rn(v.x, v.y);
    o[1] = __floats2half2_rn(v.z, v.w);
}

// ---------------- weight pre-transpose ----------------
__global__ void prep_w_k(const float* __restrict__ w1l, const float* __restrict__ w1r,
                         const float* __restrict__ w2l, const float* __restrict__ w2r) {
    int idx = blockIdx.x * blockDim.x + threadIdx.x;
    if (idx >= 2 * D * D) return;
    int k = idx >> 7, j = idx & 127;
    float v1, v2;
    if (k < D) { v1 = w1l[j * D + k];       v2 = w2l[j * D + k]; }
    else       { v1 = w1r[j * D + (k - D)]; v2 = w2r[j * D + (k - D)]; }
    g_wt1[idx] = v1;
    g_wt2[idx] = v2;
}

// ---------------- CSR build ----------------
__global__ void hist_k(const int* __restrict__ ei, int E) {
    int e = blockIdx.x * blockDim.x + threadIdx.x;
    if (e < E) atomicAdd(&g_cnt[ei[E + e]], 1);
}

__global__ void scan_local_k(int n) {
    __shared__ int sm[SCAN_B];
    int t = threadIdx.x, i = blockIdx.x * SCAN_B + t;
    int v = (i < n) ? g_cnt[i] : 0;
    sm[t] = v; __syncthreads();
    int acc = v;
    #pragma unroll
    for (int off = 1; off < SCAN_B; off <<= 1) {
        int add = (t >= off) ? sm[t - off] : 0;
        __syncthreads();
        acc += add; sm[t] = acc;
        __syncthreads();
    }
    if (i < n) g_offs[i] = acc - v;
    if (t == SCAN_B - 1) g_bsum[blockIdx.x] = acc;
}

__global__ void scan_bsum_k() {
    __shared__ int sm[64];
    int t = threadIdx.x;
    int v = (t < NBLK) ? g_bsum[t] : 0;
    sm[t] = v; __syncthreads();
    int acc = v;
    #pragma unroll
    for (int off = 1; off < 64; off <<= 1) {
        int add = (t >= off) ? sm[t - off] : 0;
        __syncthreads();
        acc += add; sm[t] = acc;
        __syncthreads();
    }
    if (t < NBLK) g_bsum[t] = acc - v;
}

__global__ void scan_add_k(int n, int E) {
    int i = blockIdx.x * blockDim.x + threadIdx.x;
    if (i < n) {
        int o = g_offs[i] + g_bsum[i / SCAN_B];
        g_offs[i] = o;
        g_cur[i] = o;
    }
    if (i == n) g_offs[n] = E;
}

__global__ void fill_k(const int* __restrict__ ei, int E) {
    int e = blockIdx.x * blockDim.x + threadIdx.x;
    if (e < E) {
        int d = ei[E + e];
        int pos = atomicAdd(&g_cur[d], 1);
        g_esrc[pos] = ei[e];
    }
}

// ---------------- gather aggregation: one warp per node, fp16 features ----------
// lane owns 4 consecutive cols (8 bytes of fp16). Accumulate fp32.
template<bool BN>
__global__ void gather_k(const __half* __restrict__ feat, int N) {
    int gw = (blockIdx.x * blockDim.x + threadIdx.x) >> 5;
    int lane = threadIdx.x & 31;
    if (gw >= N) return;
    int s0 = g_offs[gw], s1 = g_offs[gw + 1];
    float4 sc, sh;
    if (BN) {
        sc = ((const float4*)g_scale)[lane];
        sh = ((const float4*)g_shift)[lane];
    }
    const __half2* f2 = (const __half2*)feat;
    float4 acc = make_float4(0.f, 0.f, 0.f, 0.f);
    int e = s0;
    for (; e + 2 <= s1; e += 2) {
        int a = g_esrc[e], b = g_esrc[e + 1];
        __half2 a0 = __ldg(f2 + (size_t)a * 64 + lane * 2);
        __half2 a1 = __ldg(f2 + (size_t)a * 64 + lane * 2 + 1);
        __half2 b0 = __ldg(f2 + (size_t)b * 64 + lane * 2);
        __half2 b1 = __ldg(f2 + (size_t)b * 64 + lane * 2 + 1);
        float2 fa0 = __half22float2(a0), fa1 = __half22float2(a1);
        float2 fb0 = __half22float2(b0), fb1 = __half22float2(b1);
        if (BN) {
            fa0.x = fmaxf(fmaf(fa0.x, sc.x, sh.x), 0.f);
            fa0.y = fmaxf(fmaf(fa0.y, sc.y, sh.y), 0.f);
            fa1.x = fmaxf(fmaf(fa1.x, sc.z, sh.z), 0.f);
            fa1.y = fmaxf(fmaf(fa1.y, sc.w, sh.w), 0.f);
            fb0.x = fmaxf(fmaf(fb0.x, sc.x, sh.x), 0.f);
            fb0.y = fmaxf(fmaf(fb0.y, sc.y, sh.y), 0.f);
            fb1.x = fmaxf(fmaf(fb1.x, sc.z, sh.z), 0.f);
            fb1.y = fmaxf(fmaf(fb1.y, sc.w, sh.w), 0.f);
        }
        acc.x += fa0.x + fb0.x; acc.y += fa0.y + fb0.y;
        acc.z += fa1.x + fb1.x; acc.w += fa1.y + fb1.y;
    }
    if (e < s1) {
        int a = g_esrc[e];
        __half2 a0 = __ldg(f2 + (size_t)a * 64 + lane * 2);
        __half2 a1 = __ldg(f2 + (size_t)a * 64 + lane * 2 + 1);
        float2 fa0 = __half22float2(a0), fa1 = __half22float2(a1);
        if (BN) {
            fa0.x = fmaxf(fmaf(fa0.x, sc.x, sh.x), 0.f);
            fa0.y = fmaxf(fmaf(fa0.y, sc.y, sh.y), 0.f);
            fa1.x = fmaxf(fmaf(fa1.x, sc.z, sh.z), 0.f);
            fa1.y = fmaxf(fmaf(fa1.y, sc.w, sh.w), 0.f);
        }
        acc.x += fa0.x; acc.y += fa0.y; acc.z += fa1.x; acc.w += fa1.y;
    }
    float inv = 1.0f / fmaxf((float)(s1 - s0), 1.0f);
    ((float4*)g_agg)[(size_t)gw * 32 + lane] =
        make_float4(acc.x * inv, acc.y * inv, acc.z * inv, acc.w * inv);
}

// ---------------- node transform: out = [mean || self] @ WT + bias (FFMA2) ----------
// 512 threads, 16 warps; each warp: 4 rows (2 row-pairs) x 4 cols.
// smem: sInT [256][64] k-major transposed input (64KB) + sW [256][128] (128KB)
template<bool STATS, bool BN_IN>
__global__ void __launch_bounds__(TTHREADS, 1)
transform_k(const float* __restrict__ inb, const float* __restrict__ bias,
            float* __restrict__ out, int nNodes, int ntiles) {
    extern __shared__ float smem[];
    float* sInT = smem;                   // [256][TILE_N]
    float* sW   = smem + 256 * TILE_N;    // [256][128]

    const float* wt = STATS ? g_wt1 : g_wt2;
    int tid = threadIdx.x;

    // weights once, coalesced
    {
        const float4* w4 = (const float4*)wt;
        float4* s4 = (float4*)sW;
        #pragma unroll
        for (int i = 0; i < 16; i++)
            s4[tid + i * TTHREADS] = __ldg(w4 + tid + i * TTHREADS);
    }

    int tx = tid & 31, ty = tid >> 5;     // ty 0..15
    int j0 = tx * 4, n0 = ty * 4;         // 4 rows per warp
    float4 bv = __ldg((const float4*)bias + tx);

    unsigned int sInT_addr = (unsigned int)__cvta_generic_to_shared(sInT);
    unsigned int sW_addr   = (unsigned int)__cvta_generic_to_shared(sW);
    unsigned int aBase = sInT_addr + n0 * 4;
    unsigned int wBase = sW_addr + j0 * 4;

    // BN stats in registers across all tiles
    float s0 = 0, s1 = 0, s2 = 0, s3 = 0;
    float q0 = 0, q1 = 0, q2 = 0, q3 = 0;

    for (int tile = blockIdx.x; tile < ntiles; tile += gridDim.x) {
        int nb = tile * TILE_N;
        __syncthreads();

        // fill transposed tile: k rows 0..127 = mean, 128..255 = self
        #pragma unroll
        for (int i = 0; i < 8; i++) {
            int idx = tid + i * TTHREADS;   // 0..4095
            int kq = idx >> 6;              // 0..63
            int l  = idx & 63;
            int g = nb + l;
            float4 v = make_float4(0.f, 0.f, 0.f, 0.f);
            if (g < nNodes) {
                if (kq < 32) {
                    v = ((const float4*)g_agg)[(size_t)g * 32 + kq];
                } else {
                    float4 b = __ldg((const float4*)inb + (size_t)g * 32 + (kq - 32));
                    if (BN_IN) {
                        float4 scv = ((const float4*)g_scale)[kq - 32];
                        float4 shv = ((const float4*)g_shift)[kq - 32];
                        b.x = fmaxf(fmaf(b.x, scv.x, shv.x), 0.f);
                        b.y = fmaxf(fmaf(b.y, scv.y, shv.y), 0.f);
                        b.z = fmaxf(fmaf(b.z, scv.z, shv.z), 0.f);
                        b.w = fmaxf(fmaf(b.w, scv.w, shv.w), 0.f);
                    }
                    v = b;
                }
            }
            int k0 = kq * 4;
            sInT[(k0 + 0) * TILE_N + l] = v.x;
            sInT[(k0 + 1) * TILE_N + l] = v.y;
            sInT[(k0 + 2) * TILE_N + l] = v.z;
            sInT[(k0 + 3) * TILE_N + l] = v.w;
        }
        __syncthreads();

        unsigned long long acc[2][4];
        #pragma unroll
        for (int p = 0; p < 2; p++)
            #pragma unroll
            for (int j = 0; j < 4; j++) acc[p][j] = 0ULL;

        #pragma unroll 8
        for (int k = 0; k < 256; k++) {
            float w0, w1, w2, w3;
            lds_v4f(w0, w1, w2, w3, wBase + k * (D * 4));
            unsigned long long ws0 = splat2(w0), ws1 = splat2(w1),
                               ws2 = splat2(w2), ws3 = splat2(w3);
            unsigned long long p01, p23;
            lds_v2b64(p01, p23, aBase + k * (TILE_N * 4));
            acc[0][0] = fma2(p01, ws0, acc[0][0]);
            acc[0][1] = fma2(p01, ws1, acc[0][1]);
            acc[0][2] = fma2(p01, ws2, acc[0][2]);
            acc[0][3] = fma2(p01, ws3, acc[0][3]);
            acc[1][0] = fma2(p23, ws0, acc[1][0]);
            acc[1][1] = fma2(p23, ws1, acc[1][1]);
            acc[1][2] = fma2(p23, ws2, acc[1][2]);
            acc[1][3] = fma2(p23, ws3, acc[1][3]);
        }

        // epilogue
        #pragma unroll
        for (int p = 0; p < 2; p++) {
            float lo0, hi0, lo1, hi1, lo2, hi2, lo3, hi3;
            unpack2(acc[p][0], lo0, hi0);
            unpack2(acc[p][1], lo1, hi1);
            unpack2(acc[p][2], lo2, hi2);
            unpack2(acc[p][3], lo3, hi3);
            int g0 = nb + n0 + 2 * p;
            #pragma unroll
            for (int hv = 0; hv < 2; hv++) {
                int g = g0 + hv;
                if (g < nNodes) {
                    float4 v;
                    if (hv == 0) v = make_float4(lo0 + bv.x, lo1 + bv.y, lo2 + bv.z, lo3 + bv.w);
                    else         v = make_float4(hi0 + bv.x, hi1 + bv.y, hi2 + bv.z, hi3 + bv.w);
                    *(float4*)(out + (size_t)g * D + j0) = v;
                    if (STATS) {
                        // fp16 shadow for the layer-2 gather
                        __half2* hh = (__half2*)(g_hh + (size_t)g * D + j0);
                        hh[0] = __floats2half2_rn(v.x, v.y);
                        hh[1] = __floats2half2_rn(v.z, v.w);
                        s0 += v.x; q0 += v.x * v.x; s1 += v.y; q1 += v.y * v.y;
                        s2 += v.z; q2 += v.z * v.z; s3 += v.w; q3 += v.w * v.w;
                    }
                }
            }
        }
    }

    if (STATS) {
        // cross-warp smem reduction (reuse sInT), then one RED per (col,comp)
        __syncthreads();
        float* stage = sInT;               // 512*8 floats = 16KB
        stage[tid * 8 + 0] = s0; stage[tid * 8 + 1] = s1;
        stage[tid * 8 + 2] = s2; stage[tid * 8 + 3] = s3;
        stage[tid * 8 + 4] = q0; stage[tid * 8 + 5] = q1;
        stage[tid * 8 + 6] = q2; stage[tid * 8 + 7] = q3;
        __syncthreads();
        if (tid < 256) {
            int lx = tid & 31;        // lane group (col quad)
            int comp = tid >> 5;      // 0..7
            float t = 0.f;
            #pragma unroll
            for (int w = 0; w < 16; w++) t += stage[(w * 32 + lx) * 8 + comp];
            float* dst = (comp < 4) ? g_colsum : g_colsumsq;
            red_add1(dst + lx * 4 + (comp & 3), t);
        }
    }
}

// ---------------- BN finalize ----------------
__global__ void bn_finalize_k(const float* __restrict__ gamma,
                              const float* __restrict__ beta, float invN) {
    int j = threadIdx.x;
    float mu  = g_colsum[j] * invN;
    float var = g_colsumsq[j] * invN - mu * mu;
    float sc  = gamma[j] * rsqrtf(var + BN_EPS);
    g_scale[j] = sc;
    g_shift[j] = fmaf(-mu, sc, beta[j]);
}

// ---------------- launch ----------------
extern "C" void kernel_launch(void* const* d_in, const int* in_sizes, int n_in,
                              void* d_out, int out_size) {
    const float* x     = (const float*)d_in[0];
    const int*   ei    = (const int*)d_in[1];     // int32
    const float* w1l   = (const float*)d_in[2];
    const float* b1l   = (const float*)d_in[3];
    const float* w1r   = (const float*)d_in[4];
    const float* w2l   = (const float*)d_in[5];
    const float* b2l   = (const float*)d_in[6];
    const float* w2r   = (const float*)d_in[7];
    const float* gamma = (const float*)d_in[8];
    const float* beta  = (const float*)d_in[9];
    float*       out   = (float*)d_out;

    int N = in_sizes[0] / D;
    int E = in_sizes[1] / 2;
    int ntiles = (N + TILE_N - 1) / TILE_N;

    void *p_cnt, *p_cs, *p_cq, *p_h, *p_xh, *p_hh;
    cudaGetSymbolAddress(&p_cnt, g_cnt);
    cudaGetSymbolAddress(&p_cs,  g_colsum);
    cudaGetSymbolAddress(&p_cq,  g_colsumsq);
    cudaGetSymbolAddress(&p_h,   g_h);
    cudaGetSymbolAddress(&p_xh,  g_xh);
    cudaGetSymbolAddress(&p_hh,  g_hh);

    size_t smem = (size_t)(256 * TILE_N + 256 * D) * sizeof(float);  // 192KB
    cudaFuncSetAttribute(transform_k<true,  false>,
                         cudaFuncAttributeMaxDynamicSharedMemorySize, (int)smem);
    cudaFuncSetAttribute(transform_k<false, true>,
                         cudaFuncAttributeMaxDynamicSharedMemorySize, (int)smem);

    cudaMemsetAsync(p_cnt, 0, (size_t)N * sizeof(int));
    cudaMemsetAsync(p_cs,  0, D * sizeof(float));
    cudaMemsetAsync(p_cq,  0, D * sizeof(float));

    conv_half_k<<<(N * 32 + 255) / 256, 256>>>(x, N * 32);
    prep_w_k<<<(2 * D * D + 255) / 256, 256>>>(w1l, w1r, w2l, w2r);

    // CSR build (reused by both layers)
    int egrid = (E + 255) / 256;
    hist_k<<<egrid, 256>>>(ei, E);
    scan_local_k<<<(N + SCAN_B - 1) / SCAN_B, SCAN_B>>>(N);
    scan_bsum_k<<<1, 64>>>();
    scan_add_k<<<(N + 256) / 256, 256>>>(N, E);
    fill_k<<<egrid, 256>>>(ei, E);

    int ggrid = (N * 32 + 255) / 256;

    // layer 1 (gather from fp16 x-shadow; transform self path exact fp32)
    gather_k<false><<<ggrid, 256>>>((const __half*)p_xh, N);
    transform_k<true, false><<<148, TTHREADS, smem>>>(x, b1l, (float*)p_h, N, ntiles);

    bn_finalize_k<<<1, D>>>(gamma, beta, 1.0f / (float)N);

    // layer 2 (gather from fp16 h-shadow with fused relu∘bn; self path exact fp32)
    gather_k<true><<<ggrid, 256>>>((const __half*)p_hh, N);
    transform_k<false, true><<<148, TTHREADS, smem>>>((const float*)p_h, b2l, out, N, ntiles);
}

// round 6
// speedup vs baseline: 1.8111x; 1.8111x over previous
#include <cuda_runtime.h>
#include <cuda_fp16.h>
#include <cstdint>
#include <cstddef>

#define D 128
#define MAXN 50000
#define MAXE 800000
#define BN_EPS 1e-5f
#define SCAN_B 1024
#define NBLK ((MAXN + SCAN_B - 1) / SCAN_B)   // 49
#define TGRID 296                              // 2 persistent CTAs per SM

// ---------------- device scratch ----------------
__device__ __half2 g_x16[(size_t)MAXN * 64];    // fp16 x
__device__ __half2 g_h16[(size_t)MAXN * 64];    // fp16 h (later relu(bn(h)) in place)
__device__ __half2 g_agg16[(size_t)MAXN * 64];  // fp16 neighbor mean
__device__ __half2 g_bf1[16 * 16 * 32 * 2];     // layer-1 B fragments (fragment-ordered)
__device__ __half2 g_bf2[16 * 16 * 32 * 2];     // layer-2 B fragments
__device__ int    g_cnt[MAXN];
__device__ int    g_offs[MAXN + 1];
__device__ int    g_cur[MAXN];
__device__ int    g_bsum[NBLK];
__device__ int    g_esrc[MAXE];
__device__ float  g_colsum[D], g_colsumsq[D], g_scale[D], g_shift[D];

// ---------------- helpers ----------------
__device__ __forceinline__ void red_add1(float* p, float v) {
    asm volatile("red.global.add.f32 [%0], %1;" :: "l"(p), "f"(v) : "memory");
}
__device__ __forceinline__ void mma16816(float* c, uint32_t a0, uint32_t a1,
                                         uint32_t a2, uint32_t a3,
                                         uint32_t b0, uint32_t b1) {
    asm volatile("mma.sync.aligned.m16n8k16.row.col.f32.f16.f16.f32 "
                 "{%0,%1,%2,%3}, {%4,%5,%6,%7}, {%8,%9}, {%0,%1,%2,%3};"
                 : "+f"(c[0]), "+f"(c[1]), "+f"(c[2]), "+f"(c[3])
                 : "r"(a0), "r"(a1), "r"(a2), "r"(a3), "r"(b0), "r"(b1));
}

// ---------------- fp32 -> fp16 conversion of x ----------------
__global__ void conv_half_k(const float* __restrict__ x, int n4) {
    int i = blockIdx.x * blockDim.x + threadIdx.x;
    if (i >= n4) return;
    float4 v = __ldg((const float4*)x + i);
    g_x16[(size_t)i * 2]     = __floats2half2_rn(v.x, v.y);
    g_x16[(size_t)i * 2 + 1] = __floats2half2_rn(v.z, v.w);
}

// ---------------- B fragment precompute (both layers) ----------------
// m16n8k16 B fragment: lane t holds {B[k0+2(t%4)][n], B[k0+2(t%4)+1][n]} (reg0)
// and same at k+8 (reg1), n = nt*8 + t/4.  B[k][n] = W_cat[n][k], W_cat=[wl;wr].
__global__ void prep_bfrag_k(const float* __restrict__ w1l, const float* __restrict__ w1r,
                             const float* __restrict__ w2l, const float* __restrict__ w2r) {
    int idx = blockIdx.x * blockDim.x + threadIdx.x;   // 0..16383
    if (idx >= 16384) return;
    int layer = idx >> 13;
    int slot  = idx & 8191;          // (ks*16+nt)*32 + lane
    int lane  = slot & 31;
    int fk    = slot >> 5;
    int ks = fk >> 4, nt = fk & 15;
    int n  = nt * 8 + (lane >> 2);
    int k0 = ks * 16 + 2 * (lane & 3);
    const float* wl = layer ? w2l : w1l;
    const float* wr = layer ? w2r : w1r;
    auto W = [&](int k) { return (k < 128) ? wl[n * 128 + k] : wr[n * 128 + k - 128]; };
    __half2* dst = (layer ? g_bf2 : g_bf1) + (size_t)slot * 2;
    dst[0] = __floats2half2_rn(W(k0),     W(k0 + 1));
    dst[1] = __floats2half2_rn(W(k0 + 8), W(k0 + 9));
}

// ---------------- CSR build ----------------
__global__ void hist_k(const int* __restrict__ ei, int E) {
    int e = blockIdx.x * blockDim.x + threadIdx.x;
    if (e < E) atomicAdd(&g_cnt[ei[E + e]], 1);
}

__global__ void scan_local_k(int n) {
    __shared__ int sm[SCAN_B];
    int t = threadIdx.x, i = blockIdx.x * SCAN_B + t;
    int v = (i < n) ? g_cnt[i] : 0;
    sm[t] = v; __syncthreads();
    int acc = v;
    #pragma unroll
    for (int off = 1; off < SCAN_B; off <<= 1) {
        int add = (t >= off) ? sm[t - off] : 0;
        __syncthreads();
        acc += add; sm[t] = acc;
        __syncthreads();
    }
    if (i < n) g_offs[i] = acc - v;
    if (t == SCAN_B - 1) g_bsum[blockIdx.x] = acc;
}

__global__ void scan_bsum_k() {
    __shared__ int sm[64];
    int t = threadIdx.x;
    int v = (t < NBLK) ? g_bsum[t] : 0;
    sm[t] = v; __syncthreads();
    int acc = v;
    #pragma unroll
    for (int off = 1; off < 64; off <<= 1) {
        int add = (t >= off) ? sm[t - off] : 0;
        __syncthreads();
        acc += add; sm[t] = acc;
        __syncthreads();
    }
    if (t < NBLK) g_bsum[t] = acc - v;
}

__global__ void scan_add_k(int n, int E) {
    int i = blockIdx.x * blockDim.x + threadIdx.x;
    if (i < n) {
        int o = g_offs[i] + g_bsum[i / SCAN_B];
        g_offs[i] = o;
        g_cur[i] = o;
    }
    if (i == n) g_offs[n] = E;
}

__global__ void fill_k(const int* __restrict__ ei, int E) {
    int e = blockIdx.x * blockDim.x + threadIdx.x;
    if (e < E) {
        int d = ei[E + e];
        int pos = atomicAdd(&g_cur[d], 1);
        g_esrc[pos] = ei[e];
    }
}

// ---------------- gather: one warp per node, 1x LDG.64 per edge per lane ---------
__global__ void gather_k(const __half2* __restrict__ feat, int N) {
    int gw = (blockIdx.x * blockDim.x + threadIdx.x) >> 5;
    int lane = threadIdx.x & 31;
    if (gw >= N) return;
    int s0 = g_offs[gw], s1 = g_offs[gw + 1];
    const uint2* f = (const uint2*)feat;            // row = 32 uint2 (256B)
    float4 acc = make_float4(0.f, 0.f, 0.f, 0.f);
    int e = s0;
    for (; e + 2 <= s1; e += 2) {
        int a = g_esrc[e], b = g_esrc[e + 1];
        uint2 va = __ldg(f + (size_t)a * 32 + lane);
        uint2 vb = __ldg(f + (size_t)b * 32 + lane);
        float2 fa0 = __half22float2(*(__half2*)&va.x);
        float2 fa1 = __half22float2(*(__half2*)&va.y);
        float2 fb0 = __half22float2(*(__half2*)&vb.x);
        float2 fb1 = __half22float2(*(__half2*)&vb.y);
        acc.x += fa0.x + fb0.x; acc.y += fa0.y + fb0.y;
        acc.z += fa1.x + fb1.x; acc.w += fa1.y + fb1.y;
    }
    if (e < s1) {
        int a = g_esrc[e];
        uint2 va = __ldg(f + (size_t)a * 32 + lane);
        float2 fa0 = __half22float2(*(__half2*)&va.x);
        float2 fa1 = __half22float2(*(__half2*)&va.y);
        acc.x += fa0.x; acc.y += fa0.y; acc.z += fa1.x; acc.w += fa1.y;
    }
    float inv = 1.0f / fmaxf((float)(s1 - s0), 1.0f);
    uint2 o;
    *(__half2*)&o.x = __floats2half2_rn(acc.x * inv, acc.y * inv);
    *(__half2*)&o.y = __floats2half2_rn(acc.z * inv, acc.w * inv);
    ((uint2*)g_agg16)[(size_t)gw * 32 + lane] = o;
}

// ---------------- HMMA node transform ----------------
// C[m 128][n 128] = A[m][k 256] x B[k][n] + bias; A = [agg || self] fp16 from global,
// B = fragment-ordered fp16 in smem. 8 warps, each owns 16 rows x 128 cols.
template<bool OUT_HALF>
__global__ void __launch_bounds__(256, 2)
mma_transform_k(const uint32_t* __restrict__ aggH,   // [m][64] half2-as-u32
                const uint32_t* __restrict__ selfH,
                const uint2* __restrict__ bfrag,     // 8192 x 8B fragments
                const float* __restrict__ bias,
                float* __restrict__ outF, __half2* __restrict__ outH,
                int nNodes, int ntiles) {
    extern __shared__ char smraw[];
    uint2* sB = (uint2*)smraw;                        // 64KB
    float* sBias = (float*)(smraw + 65536);
    int tid = threadIdx.x;
    for (int i = tid; i < 8192; i += 256) sB[i] = __ldg(bfrag + i);
    if (tid < 128) sBias[tid] = __ldg(bias + tid);
    __syncthreads();

    int warp = tid >> 5, lane = tid & 31;
    int r = lane >> 2, c = lane & 3;

    for (int tile = blockIdx.x; tile < ntiles; tile += gridDim.x) {
        int m0 = tile * 128 + warp * 16;
        size_t row0 = (size_t)min(m0 + r,     nNodes - 1);
        size_t row1 = (size_t)min(m0 + r + 8, nNodes - 1);
        const uint32_t* p0a = aggH  + row0 * 64 + c;
        const uint32_t* p1a = aggH  + row1 * 64 + c;
        const uint32_t* p0s = selfH + row0 * 64 + c;
        const uint32_t* p1s = selfH + row1 * 64 + c;

        float acc[16][4];
        #pragma unroll
        for (int nt = 0; nt < 16; nt++)
            #pragma unroll
            for (int q = 0; q < 4; q++) acc[nt][q] = 0.f;

        #pragma unroll
        for (int ks = 0; ks < 16; ks++) {
            const uint32_t* p0 = (ks < 8) ? p0a + ks * 8 : p0s + (ks - 8) * 8;
            const uint32_t* p1 = (ks < 8) ? p1a + ks * 8 : p1s + (ks - 8) * 8;
            uint32_t a0 = __ldg(p0), a2 = __ldg(p0 + 4);
            uint32_t a1 = __ldg(p1), a3 = __ldg(p1 + 4);
            const uint2* bp = sB + ks * 512 + lane;
            #pragma unroll
            for (int nt = 0; nt < 16; nt++) {
                uint2 b = bp[nt * 32];
                mma16816(acc[nt], a0, a1, a2, a3, b.x, b.y);
            }
        }

        bool ok0 = (m0 + r)     < nNodes;
        bool ok1 = (m0 + r + 8) < nNodes;
        #pragma unroll
        for (int nt = 0; nt < 16; nt++) {
            int j = nt * 8 + 2 * c;
            float b0 = sBias[j], b1 = sBias[j + 1];
            float v0 = acc[nt][0] + b0, v1 = acc[nt][1] + b1;
            float v2 = acc[nt][2] + b0, v3 = acc[nt][3] + b1;
            if (OUT_HALF) {
                if (ok0) outH[(size_t)(m0 + r)     * 64 + (j >> 1)] = __floats2half2_rn(v0, v1);
                if (ok1) outH[(size_t)(m0 + r + 8) * 64 + (j >> 1)] = __floats2half2_rn(v2, v3);
            } else {
                if (ok0) *(float2*)(outF + (size_t)(m0 + r)     * 128 + j) = make_float2(v0, v1);
                if (ok1) *(float2*)(outF + (size_t)(m0 + r + 8) * 128 + j) = make_float2(v2, v3);
            }
        }
    }
}

// ---------------- BN column stats over fp16 h ----------------
__global__ void stats_half_k(int N) {
    int c2  = threadIdx.x & 63;
    int sub = threadIdx.x >> 6;      // 0..3
    float sx = 0.f, sy = 0.f, qx = 0.f, qy = 0.f;
    for (int row = blockIdx.x * 4 + sub; row < N; row += gridDim.x * 4) {
        float2 f = __half22float2(g_h16[(size_t)row * 64 + c2]);
        sx += f.x; sy += f.y; qx += f.x * f.x; qy += f.y * f.y;
    }
    red_add1(g_colsum   + 2 * c2,     sx);
    red_add1(g_colsum   + 2 * c2 + 1, sy);
    red_add1(g_colsumsq + 2 * c2,     qx);
    red_add1(g_colsumsq + 2 * c2 + 1, qy);
}

// ---------------- BN finalize ----------------
__global__ void bn_finalize_k(const float* __restrict__ gamma,
                              const float* __restrict__ beta, float invN) {
    int j = threadIdx.x;
    float mu  = g_colsum[j] * invN;
    float var = g_colsumsq[j] * invN - mu * mu;
    float sc  = gamma[j] * rsqrtf(var + BN_EPS);
    g_scale[j] = sc;
    g_shift[j] = fmaf(-mu, sc, beta[j]);
}

// ---------------- relu(bn(h)) in place on fp16 h ----------------
__global__ void relu_bn_k(int total2) {
    int i = blockIdx.x * blockDim.x + threadIdx.x;
    if (i >= total2) return;
    int c2 = i & 63;
    float2 sc = ((const float2*)g_scale)[c2];
    float2 sh = ((const float2*)g_shift)[c2];
    float2 f = __half22float2(g_h16[i]);
    f.x = fmaxf(fmaf(f.x, sc.x, sh.x), 0.f);
    f.y = fmaxf(fmaf(f.y, sc.y, sh.y), 0.f);
    g_h16[i] = __floats2half2_rn(f.x, f.y);
}

// ---------------- launch ----------------
extern "C" void kernel_launch(void* const* d_in, const int* in_sizes, int n_in,
                              void* d_out, int out_size) {
    const float* x     = (const float*)d_in[0];
    const int*   ei    = (const int*)d_in[1];     // int32
    const float* w1l   = (const float*)d_in[2];
    const float* b1l   = (const float*)d_in[3];
    const float* w1r   = (const float*)d_in[4];
    const float* w2l   = (const float*)d_in[5];
    const float* b2l   = (const float*)d_in[6];
    const float* w2r   = (const float*)d_in[7];
    const float* gamma = (const float*)d_in[8];
    const float* beta  = (const float*)d_in[9];
    float*       out   = (float*)d_out;

    int N = in_sizes[0] / D;
    int E = in_sizes[1] / 2;
    int ntiles = (N + 127) / 128;

    void *p_cnt, *p_cs, *p_cq, *p_x16, *p_h16, *p_agg16, *p_bf1, *p_bf2;
    cudaGetSymbolAddress(&p_cnt,   g_cnt);
    cudaGetSymbolAddress(&p_cs,    g_colsum);
    cudaGetSymbolAddress(&p_cq,    g_colsumsq);
    cudaGetSymbolAddress(&p_x16,   g_x16);
    cudaGetSymbolAddress(&p_h16,   g_h16);
    cudaGetSymbolAddress(&p_agg16, g_agg16);
    cudaGetSymbolAddress(&p_bf1,   g_bf1);
    cudaGetSymbolAddress(&p_bf2,   g_bf2);

    int smem = 65536 + 512;
    cudaFuncSetAttribute(mma_transform_k<true>,
                         cudaFuncAttributeMaxDynamicSharedMemorySize, smem);
    cudaFuncSetAttribute(mma_transform_k<false>,
                         cudaFuncAttributeMaxDynamicSharedMemorySize, smem);

    cudaMemsetAsync(p_cnt, 0, (size_t)N * sizeof(int));
    cudaMemsetAsync(p_cs,  0, D * sizeof(float));
    cudaMemsetAsync(p_cq,  0, D * sizeof(float));

    conv_half_k<<<(N * 32 + 255) / 256, 256>>>(x, N * 32);
    prep_bfrag_k<<<64, 256>>>(w1l, w1r, w2l, w2r);

    // CSR build (reused by both layers)
    int egrid = (E + 255) / 256;
    hist_k<<<egrid, 256>>>(ei, E);
    scan_local_k<<<(N + SCAN_B - 1) / SCAN_B, SCAN_B>>>(N);
    scan_bsum_k<<<1, 64>>>();
    scan_add_k<<<(N + 256) / 256, 256>>>(N, E);
    fill_k<<<egrid, 256>>>(ei, E);

    int ggrid = (N * 32 + 255) / 256;

    // layer 1: h = mean(x_nbr)@W1l + b1 + x@W1r   (all fp16 inputs, fp32 acc)
    gather_k<<<ggrid, 256>>>((const __half2*)p_x16, N);
    mma_transform_k<true><<<TGRID, 256, smem>>>(
        (const uint32_t*)p_agg16, (const uint32_t*)p_x16,
        (const uint2*)p_bf1, b1l, nullptr, (__half2*)p_h16, N, ntiles);

    // BN
    stats_half_k<<<148, 256>>>(N);
    bn_finalize_k<<<1, D>>>(gamma, beta, 1.0f / (float)N);
    relu_bn_k<<<(N * 64 + 255) / 256, 256>>>(N * 64);

    // layer 2: out = mean(rbh_nbr)@W2l + b2 + rbh@W2r
    gather_k<<<ggrid, 256>>>((const __half2*)p_h16, N);
    mma_transform_k<false><<<TGRID, 256, smem>>>(
        (const uint32_t*)p_agg16, (const uint32_t*)p_h16,
        (const uint2*)p_bf2, b2l, out, nullptr, N, ntiles);
}